// round 9
// baseline (speedup 1.0000x reference)
#include <cuda_runtime.h>

// Problem constants
#define NB      768          // N*C
#define NB4     3072         // quarter-tiles
#define HH      62
#define WW      64
#define KCODE   256
#define NPAIR   128
#define CHUNKS_PER_B 1024    // W * Hp / D
#define M_TOTAL (NB * CHUNKS_PER_B)          // 786432
#define QL_ELEMS (NB * HH * WW)              // 3047424
#define OFF_MSE   QL_ELEMS
#define OFF_INDS  (QL_ELEMS + 1)
#define OFF_RATE  (OFF_INDS + M_TOTAL)
#define OFF_PRIOR (OFF_RATE + 1)
#define OFF_PARAM (OFF_RATE + 2)
#define MSE_COUNT 3145728.0f                 // NB * 1024 * 4

#define NEG_INV_LN2 (-1.4426950408889634f)
#define INV_LMBDA   100.0f

typedef unsigned long long u64;

// Deterministic per-tile partials + completion counter
__device__ float g_pmse[NB4];
__device__ float g_prate[NB4];
__device__ int   g_count;        // zero-init; last block resets it -> graph-replayable

__device__ __forceinline__ u64 pack2(float lo, float hi) {
    u64 r; asm("mov.b64 %0,{%1,%2};" : "=l"(r) : "f"(lo), "f"(hi)); return r;
}
__device__ __forceinline__ void unpack2(u64 v, float& lo, float& hi) {
    asm("mov.b64 {%0,%1},%2;" : "=f"(lo), "=f"(hi) : "l"(v));
}
__device__ __forceinline__ float lo_of(u64 v) {
    float lo, hi; unpack2(v, lo, hi); return lo;
}
// packed dual-fp32 FMA (Blackwell f32x2 pipe; 2 MACs per issue slot)
__device__ __forceinline__ u64 fma2(u64 a, u64 b, u64 c) {
    u64 d; asm("fma.rn.f32x2 %0,%1,%2,%3;" : "=l"(d) : "l"(a), "l"(b), "l"(c)); return d;
}

__global__ __launch_bounds__(128)
void vq_main(const float* __restrict__ lat,
             const float* __restrict__ cb,
             const float* __restrict__ lpmf,
             float* __restrict__ out)
{
    // Packed codebook: pair p -> {-2*c[2p][d], -2*c[2p+1][d]} split for LDS.128 loads
    __shared__ ulonglong2 s_n01[NPAIR];   // {n_d0, n_d1}
    __shared__ ulonglong2 s_n23[NPAIR];   // {n_d2, n_d3}
    __shared__ u64        s_bias[NPAIR];
    __shared__ float4     s_cw[KCODE];
    __shared__ float      s_l2p[KCODE];
    __shared__ float      s_ind[256];     // this quarter's 256 chunk indices
    __shared__ float      s_rm[4];
    __shared__ float      s_rr[4];
    __shared__ int        s_last;

    const int tid = threadIdx.x;         // 0..127
    const int blk = blockIdx.x;          // 0..3071
    const int b   = blk >> 2;            // 0..767
    const int wq  = blk & 3;             // quarter: w in [wq*16, wq*16+16)

    // ---- codebook prep (tiny; stays hot in L2 across blocks) ----
    #pragma unroll
    for (int i = 0; i < 2; ++i) {
        const int k = tid * 2 + i;
        float4 ck = *(const float4*)(cb + k * 4);
        s_cw[k]  = ck;
        s_l2p[k] = lpmf[k] * NEG_INV_LN2;
    }
    {
        const int p = tid;               // 128 pairs, 128 threads
        float4 c0 = *(const float4*)(cb + (2 * p) * 4);
        float4 c1 = *(const float4*)(cb + (2 * p + 1) * 4);
        ulonglong2 a, bq;
        a.x  = pack2(-2.f * c0.x, -2.f * c1.x);
        a.y  = pack2(-2.f * c0.y, -2.f * c1.y);
        bq.x = pack2(-2.f * c0.z, -2.f * c1.z);
        bq.y = pack2(-2.f * c0.w, -2.f * c1.w);
        s_n01[p] = a;
        s_n23[p] = bq;
        float b0 = c0.x*c0.x + c0.y*c0.y + c0.z*c0.z + c0.w*c0.w
                 + lpmf[2*p]     * NEG_INV_LN2 * INV_LMBDA;
        float b1 = c1.x*c1.x + c1.y*c1.y + c1.z*c1.z + c1.w*c1.w
                 + lpmf[2*p + 1] * NEG_INV_LN2 * INV_LMBDA;
        s_bias[p] = pack2(b0, b1);
    }
    __syncthreads();

    // ---- thread -> 2 chunks (c, w0..w0+1) ----
    const int wl = (tid & 7) * 2;        // local w pair within this quarter
    const int w0 = wq * 16 + wl;         // global w
    const int c  = tid >> 3;             // 0..15 chunk row-group

    const int h0 = 4 * c, h1 = h0 + 1, h2 = h0 + 2, h3 = h0 + 3;
    const int s2 = (h2 < HH) ? h2 : h2 - 2;   // c==15: 62 -> 60
    const int s3 = (h3 < HH) ? h3 : h3 - 2;   // c==15: 63 -> 61

    const float* base = lat + (size_t)b * (HH * WW) + w0;
    float2 v0 = *(const float2*)(base + h0 * WW);
    float2 v1 = *(const float2*)(base + h1 * WW);
    float2 v2 = *(const float2*)(base + s2 * WW);
    float2 v3 = *(const float2*)(base + s3 * WW);

    // chunk j (w = w0+j) has elements (v0[j], v1[j], v2[j], v3[j]); pack duplicated
    u64 xq0[2], xq1[2], xq2[2], xq3[2];
    xq0[0] = pack2(v0.x, v0.x);  xq0[1] = pack2(v0.y, v0.y);
    xq1[0] = pack2(v1.x, v1.x);  xq1[1] = pack2(v1.y, v1.y);
    xq2[0] = pack2(v2.x, v2.x);  xq2[1] = pack2(v2.y, v2.y);
    xq3[0] = pack2(v3.x, v3.x);  xq3[1] = pack2(v3.y, v3.y);

    // ---- main loop: value-only min over 32 groups of 8 codewords ----
    // score_k = (||c_k||^2 + log2_pmf_k/lambda) - 2 * <x, c_k>
    float best[2] = {3.4e38f, 3.4e38f};
    int   bgrp[2] = {0, 0};

    #pragma unroll 4
    for (int g = 0; g < 32; ++g) {
        float pm[2][4];
        #pragma unroll
        for (int q = 0; q < 4; ++q) {
            const int p = (g << 2) + q;
            ulonglong2 n01 = s_n01[p];
            ulonglong2 n23 = s_n23[p];
            u64 bias = s_bias[p];
            #pragma unroll
            for (int j = 0; j < 2; ++j) {
                u64 a = fma2(xq0[j], n01.x, bias);
                a = fma2(xq1[j], n01.y, a);
                a = fma2(xq2[j], n23.x, a);
                a = fma2(xq3[j], n23.y, a);
                float lo, hi; unpack2(a, lo, hi);
                pm[j][q] = fminf(lo, hi);
            }
        }
        #pragma unroll
        for (int j = 0; j < 2; ++j) {
            float gm = fminf(fminf(pm[j][0], pm[j][1]), fminf(pm[j][2], pm[j][3]));
            // strict < keeps the earliest group on ties (first-index-wins)
            if (gm < best[j]) { best[j] = gm; bgrp[j] = g; }
        }
    }

    // ---- index recovery: recompute the winning group's 8 scores bit-exactly,
    //      descending overwrite-on-equality -> lowest k wins (jnp.argmin ties) ----
    int bi[2];
    #pragma unroll
    for (int j = 0; j < 2; ++j) {
        int idx = 0;
        const int pbase = bgrp[j] << 2;
        #pragma unroll
        for (int q = 3; q >= 0; --q) {
            const int p = pbase + q;
            ulonglong2 n01 = s_n01[p];
            ulonglong2 n23 = s_n23[p];
            u64 bias = s_bias[p];
            u64 a = fma2(xq0[j], n01.x, bias);
            a = fma2(xq1[j], n01.y, a);
            a = fma2(xq2[j], n23.x, a);
            a = fma2(xq3[j], n23.y, a);
            float lo, hi; unpack2(a, lo, hi);
            if (hi == best[j]) idx = 2 * p + 1;
            if (lo == best[j]) idx = 2 * p;
        }
        bi[j] = idx;
    }

    // ---- gather chosen codewords ----
    float4 q0 = s_cw[bi[0]];   // chunk at w0
    float4 q1 = s_cw[bi[1]];   // chunk at w0+1

    // ql writes: row d at (h_d, w0..w0+1) = (q0[d], q1[d]) -> STG.64
    float* oql = out + (size_t)b * (HH * WW) + w0;
    *(float2*)(oql + h0 * WW) = make_float2(q0.x, q1.x);
    *(float2*)(oql + h1 * WW) = make_float2(q0.y, q1.y);
    if (h2 < HH) *(float2*)(oql + h2 * WW) = make_float2(q0.z, q1.z);
    if (h3 < HH) *(float2*)(oql + h3 * WW) = make_float2(q0.w, q1.w);

    // mse / rate partials (all 8 elements count, incl. padded duplicates)
    float lm, lr;
    {
        float d00 = q0.x - v0.x, d01 = q0.y - v1.x, d02 = q0.z - v2.x, d03 = q0.w - v3.x;
        float d10 = q1.x - v0.y, d11 = q1.y - v1.y, d12 = q1.z - v2.y, d13 = q1.w - v3.y;
        lm = d00*d00 + d01*d01 + d02*d02 + d03*d03
           + d10*d10 + d11*d11 + d12*d12 + d13*d13;
        lr = s_l2p[bi[0]] + s_l2p[bi[1]];
    }

    // inds: flat m = b*1024 + w*16 + c; this quarter owns [b*1024 + wq*256, +256)
    s_ind[(wl + 0) * 16 + c] = (float)bi[0];
    s_ind[(wl + 1) * 16 + c] = (float)bi[1];

    // ---- deterministic block reduction (4 warps) ----
    #pragma unroll
    for (int o = 16; o > 0; o >>= 1) {
        lm += __shfl_down_sync(0xFFFFFFFFu, lm, o);
        lr += __shfl_down_sync(0xFFFFFFFFu, lr, o);
    }
    if ((tid & 31) == 0) { s_rm[tid >> 5] = lm; s_rr[tid >> 5] = lr; }
    __syncthreads();

    // coalesced inds writeout (256 floats by 128 threads)
    float* oind = out + OFF_INDS + (size_t)b * CHUNKS_PER_B + wq * 256;
    oind[tid]       = s_ind[tid];
    oind[tid + 128] = s_ind[tid + 128];

    if (tid == 0) {
        g_pmse[blk]  = (s_rm[0] + s_rm[1]) + (s_rm[2] + s_rm[3]);
        g_prate[blk] = (s_rr[0] + s_rr[1]) + (s_rr[2] + s_rr[3]);
        __threadfence();
        int v = atomicAdd(&g_count, 1);
        s_last = (v == NB4 - 1);
    }
    __syncthreads();

    // ---- fused finalize: last block reduces the 3072 partials (fixed order) ----
    if (s_last) {
        __threadfence();   // acquire: make all blocks' partials visible
        float a = 0.f, r = 0.f;
        #pragma unroll
        for (int i = 0; i < 24; ++i) {      // 3072 = 128*24, fixed order
            a += g_pmse[tid + i * 128];
            r += g_prate[tid + i * 128];
        }
        s_ind[tid]       = a;               // reuse smem
        s_ind[tid + 128] = r;
        __syncthreads();
        #pragma unroll
        for (int s = 64; s > 0; s >>= 1) {
            if (tid < s) {
                s_ind[tid]       += s_ind[tid + s];
                s_ind[128 + tid] += s_ind[128 + tid + s];
            }
            __syncthreads();
        }
        if (tid == 0) {
            out[OFF_MSE]   = s_ind[0] * (1.0f / MSE_COUNT);
            out[OFF_RATE]  = s_ind[128];
            out[OFF_PRIOR] = 0.f;
            out[OFF_PARAM] = 0.f;
            g_count = 0;   // reset for next graph replay
        }
    }
}

extern "C" void kernel_launch(void* const* d_in, const int* in_sizes, int n_in,
                              void* d_out, int out_size)
{
    const float* lat  = (const float*)d_in[0];   // latents  (4,192,62,64)
    const float* cb   = (const float*)d_in[1];   // codebook (256,4)
    const float* lpmf = (const float*)d_in[2];   // log_pmf  (256,)
    float* out = (float*)d_out;

    vq_main<<<NB4, 128>>>(lat, cb, lpmf, out);
}